// round 1
// baseline (speedup 1.0000x reference)
#include <cuda_runtime.h>

// WaveNet-style dilated causal conv stack.
// B=64, T=4096, C=8, 10 layers, dilation 2^i, kernel 3, output = last 128 samples.
// Only the trailing L=2176 timesteps influence the output (receptive field 2046 + 128 + align).
// One CTA per batch element; full residual state kept in SMEM.

#define NTH 256
#define LBUF 2176          // trailing window kept in shared memory
#define FRAME 128
#define TFULL 4096

// ---- weights in constant memory (copied in kernel_launch via memcpy nodes) ----
__constant__ float C0[24];     // (3,1,8): [w*8+co]
__constant__ float CK[1728];   // (9,3,8,8): [(((i-1)*3+w)*8+ci)*8+co]
__constant__ float CB[80];     // (10,8)
__constant__ float IOK[576];   // (9,1,8,8): [(i*8+ci)*8+co]
__constant__ float IOB[72];    // (9,8)
__constant__ float MIX[80];    // (80,)
__constant__ float MIXB[1];    // (1,)

extern __shared__ float smem[];

__global__ __launch_bounds__(NTH) void wavenet_kernel(const float* __restrict__ X,
                                                      float* __restrict__ out) {
    float* xb   = smem;                   // LBUF
    float* h    = smem + LBUF;            // 8*LBUF, layout h[c*LBUF + l]
    float* yb   = smem + LBUF * 9;        // 8*LBUF
    float* oacc = smem + LBUF * 17;       // FRAME

    const int tid = threadIdx.x;
    const int b   = blockIdx.x;
    const float* x = X + b * TFULL + (TFULL - LBUF);

    for (int l = tid; l < LBUF; l += NTH) xb[l] = x[l];
    if (tid < FRAME) oacc[tid] = MIXB[0];
    __syncthreads();

    // ---------------- layer 0: conv (1->8), relu, mixer; then io + residual(+x) ----------------
    for (int l = 2 + tid; l < LBUF; l += NTH) {
        float x0 = xb[l - 2], x1 = xb[l - 1], x2 = xb[l];
        float acc[8];
#pragma unroll
        for (int co = 0; co < 8; co++) {
            float a = CB[co];
            a = fmaf(x0, C0[co], a);
            a = fmaf(x1, C0[8 + co], a);
            a = fmaf(x2, C0[16 + co], a);
            a = fmaxf(a, 0.0f);
            acc[co] = a;
            yb[co * LBUF + l] = a;
        }
        if (l >= LBUF - FRAME) {
            float m = 0.0f;
#pragma unroll
            for (int co = 0; co < 8; co++) m = fmaf(acc[co], MIX[co], m);
            oacc[l - (LBUF - FRAME)] += m;
        }
    }
    __syncthreads();
    for (int l = 2 + tid; l < LBUF; l += NTH) {
        float yv[8];
#pragma unroll
        for (int c = 0; c < 8; c++) yv[c] = yb[c * LBUF + l];
        float xv = xb[l];
#pragma unroll
        for (int co = 0; co < 8; co++) {
            float a = IOB[co] + xv;
#pragma unroll
            for (int ci = 0; ci < 8; ci++) a = fmaf(yv[ci], IOK[ci * 8 + co], a);
            h[co * LBUF + l] = a;
        }
    }
    __syncthreads();

    // ---------------- layers 1..9 ----------------
#pragma unroll
    for (int i = 1; i < 10; i++) {
        const int d = 1 << i;
        const int S = 2 * ((2 << i) - 1);  // 2*(2^(i+1)-1)

        // phase 1: dilated conv 8->8 + relu + mixer accumulation
        for (int l = S + tid; l < LBUF; l += NTH) {
            float acc[8];
#pragma unroll
            for (int co = 0; co < 8; co++) acc[co] = CB[i * 8 + co];
#pragma unroll
            for (int w = 0; w < 3; w++) {
                const int off = (2 - w) * d;
#pragma unroll
                for (int ci = 0; ci < 8; ci++) {
                    float v = h[ci * LBUF + l - off];
#pragma unroll
                    for (int co = 0; co < 8; co++)
                        acc[co] = fmaf(v, CK[(((i - 1) * 3 + w) * 8 + ci) * 8 + co], acc[co]);
                }
            }
#pragma unroll
            for (int co = 0; co < 8; co++) {
                acc[co] = fmaxf(acc[co], 0.0f);
                yb[co * LBUF + l] = acc[co];
            }
            if (l >= LBUF - FRAME) {
                float m = 0.0f;
#pragma unroll
                for (int co = 0; co < 8; co++) m = fmaf(acc[co], MIX[i * 8 + co], m);
                oacc[l - (LBUF - FRAME)] += m;
            }
        }
        __syncthreads();

        // phase 2: io 8->8 + residual (skip for last layer)
        if (i < 9) {
            for (int l = S + tid; l < LBUF; l += NTH) {
                float yv[8];
#pragma unroll
                for (int c = 0; c < 8; c++) yv[c] = yb[c * LBUF + l];
                float nh[8];
#pragma unroll
                for (int co = 0; co < 8; co++) {
                    float a = IOB[i * 8 + co] + h[co * LBUF + l];
#pragma unroll
                    for (int ci = 0; ci < 8; ci++)
                        a = fmaf(yv[ci], IOK[(i * 8 + ci) * 8 + co], a);
                    nh[co] = a;
                }
#pragma unroll
                for (int co = 0; co < 8; co++) h[co * LBUF + l] = nh[co];
            }
            __syncthreads();
        }
    }

    for (int j = tid; j < FRAME; j += NTH) out[b * FRAME + j] = oacc[j];
}

static const int SMEM_BYTES = (LBUF * 17 + FRAME) * (int)sizeof(float);

extern "C" void kernel_launch(void* const* d_in, const int* in_sizes, int n_in,
                              void* d_out, int out_size) {
    (void)in_sizes; (void)n_in; (void)out_size;
    const float* x = (const float*)d_in[0];

    cudaFuncSetAttribute(wavenet_kernel, cudaFuncAttributeMaxDynamicSharedMemorySize, SMEM_BYTES);

    cudaMemcpyToSymbolAsync(C0,   d_in[1],   24 * sizeof(float), 0, cudaMemcpyDeviceToDevice, 0);
    cudaMemcpyToSymbolAsync(CK,   d_in[2], 1728 * sizeof(float), 0, cudaMemcpyDeviceToDevice, 0);
    cudaMemcpyToSymbolAsync(CB,   d_in[3],   80 * sizeof(float), 0, cudaMemcpyDeviceToDevice, 0);
    cudaMemcpyToSymbolAsync(IOK,  d_in[4],  576 * sizeof(float), 0, cudaMemcpyDeviceToDevice, 0);
    cudaMemcpyToSymbolAsync(IOB,  d_in[5],   72 * sizeof(float), 0, cudaMemcpyDeviceToDevice, 0);
    cudaMemcpyToSymbolAsync(MIX,  d_in[6],   80 * sizeof(float), 0, cudaMemcpyDeviceToDevice, 0);
    cudaMemcpyToSymbolAsync(MIXB, d_in[7],    1 * sizeof(float), 0, cudaMemcpyDeviceToDevice, 0);

    wavenet_kernel<<<64, NTH, SMEM_BYTES>>>(x, (float*)d_out);
}

// round 2
// speedup vs baseline: 1.2075x; 1.2075x over previous
#include <cuda_runtime.h>

// WaveNet-style dilated causal conv stack, fused conv+io per layer, ping-pong h in SMEM.
// B=64, T=4096, C=8, 10 layers, dilation 2^i, kernel 3, output = last 128 samples.

#define NTH 512
#define LBUF 2176
#define FRAME 128
#define TFULL 4096

__constant__ float C0[24];     // (3,1,8): [w*8+co]
__constant__ float CK[1728];   // (9,3,8,8): [(((i-1)*3+w)*8+ci)*8+co]
__constant__ float CB[80];     // (10,8)
__constant__ float IOK[576];   // (9,1,8,8): [(i*8+ci)*8+co]
__constant__ float IOB[72];    // (9,8)
__constant__ float MIX[80];    // (80,)
__constant__ float MIXB[1];    // (1,)

extern __shared__ float smem[];

__global__ __launch_bounds__(NTH) void wavenet_kernel(const float* __restrict__ X,
                                                      float* __restrict__ out) {
    float* xb   = smem;                    // LBUF
    float* hA   = smem + LBUF;             // 8*LBUF, layout h[c*LBUF + l]
    float* hB   = smem + LBUF * 9;         // 8*LBUF
    float* oacc = smem + LBUF * 17;        // FRAME

    const int tid = threadIdx.x;
    const int b   = blockIdx.x;
    const float* x = X + b * TFULL + (TFULL - LBUF);

    for (int l = tid; l < LBUF; l += NTH) xb[l] = x[l];
    if (tid < FRAME) oacc[tid] = MIXB[0];
    __syncthreads();

    // ---- layer 0 (fused): conv(1->8)+relu+mixer, io(8->8)+x residual -> hA ----
    for (int l = 2 + tid; l < LBUF; l += NTH) {
        float x0 = xb[l - 2], x1 = xb[l - 1], x2 = xb[l];
        float acc[8];
#pragma unroll
        for (int co = 0; co < 8; co++) {
            float a = CB[co];
            a = fmaf(x0, C0[co], a);
            a = fmaf(x1, C0[8 + co], a);
            a = fmaf(x2, C0[16 + co], a);
            acc[co] = fmaxf(a, 0.0f);
        }
        if (l >= LBUF - FRAME) {
            float m = 0.0f;
#pragma unroll
            for (int co = 0; co < 8; co++) m = fmaf(acc[co], MIX[co], m);
            oacc[l - (LBUF - FRAME)] += m;
        }
#pragma unroll
        for (int co = 0; co < 8; co++) {
            float a = IOB[co] + x2;
#pragma unroll
            for (int ci = 0; ci < 8; ci++) a = fmaf(acc[ci], IOK[ci * 8 + co], a);
            hA[co * LBUF + l] = a;
        }
    }
    __syncthreads();

    // ---- layers 1..8 (fused): dilated conv+relu+mixer, io+residual, ping-pong ----
#pragma unroll
    for (int i = 1; i < 9; i++) {
        const int d = 1 << i;
        const int S = 2 * ((2 << i) - 1);          // 2*(2^(i+1)-1)
        const float* cur = (i & 1) ? hA : hB;      // i=1 reads hA
        float*       nxt = (i & 1) ? hB : hA;

        for (int l = S + tid; l < LBUF; l += NTH) {
            float acc[8];
#pragma unroll
            for (int co = 0; co < 8; co++) acc[co] = CB[i * 8 + co];
            float hl[8];
#pragma unroll
            for (int w = 0; w < 3; w++) {
                const int off = (2 - w) * d;
#pragma unroll
                for (int ci = 0; ci < 8; ci++) {
                    float v = cur[ci * LBUF + l - off];
                    if (w == 2) hl[ci] = v;
#pragma unroll
                    for (int co = 0; co < 8; co++)
                        acc[co] = fmaf(v, CK[(((i - 1) * 3 + w) * 8 + ci) * 8 + co], acc[co]);
                }
            }
#pragma unroll
            for (int co = 0; co < 8; co++) acc[co] = fmaxf(acc[co], 0.0f);
            if (l >= LBUF - FRAME) {
                float m = 0.0f;
#pragma unroll
                for (int co = 0; co < 8; co++) m = fmaf(acc[co], MIX[i * 8 + co], m);
                oacc[l - (LBUF - FRAME)] += m;
            }
#pragma unroll
            for (int co = 0; co < 8; co++) {
                float a = IOB[i * 8 + co] + hl[co];
#pragma unroll
                for (int ci = 0; ci < 8; ci++)
                    a = fmaf(acc[ci], IOK[(i * 8 + ci) * 8 + co], a);
                nxt[co * LBUF + l] = a;
            }
        }
        __syncthreads();
    }

    // ---- layer 9: conv+relu+mixer only, last FRAME positions ----
    {
        const int i = 9;
        const int d = 512;
        const float* cur = hA;  // layer 8 (i=8, even) wrote hA
        for (int l = (LBUF - FRAME) + tid; l < LBUF; l += NTH) {
            float acc[8];
#pragma unroll
            for (int co = 0; co < 8; co++) acc[co] = CB[i * 8 + co];
#pragma unroll
            for (int w = 0; w < 3; w++) {
                const int off = (2 - w) * d;
#pragma unroll
                for (int ci = 0; ci < 8; ci++) {
                    float v = cur[ci * LBUF + l - off];
#pragma unroll
                    for (int co = 0; co < 8; co++)
                        acc[co] = fmaf(v, CK[(((i - 1) * 3 + w) * 8 + ci) * 8 + co], acc[co]);
                }
            }
            float m = 0.0f;
#pragma unroll
            for (int co = 0; co < 8; co++) m = fmaf(fmaxf(acc[co], 0.0f), MIX[i * 8 + co], m);
            oacc[l - (LBUF - FRAME)] += m;
        }
    }
    __syncthreads();

    for (int j = tid; j < FRAME; j += NTH) out[b * FRAME + j] = oacc[j];
}

static const int SMEM_BYTES = (LBUF * 17 + FRAME) * (int)sizeof(float);

extern "C" void kernel_launch(void* const* d_in, const int* in_sizes, int n_in,
                              void* d_out, int out_size) {
    (void)in_sizes; (void)n_in; (void)out_size;
    const float* x = (const float*)d_in[0];

    cudaFuncSetAttribute(wavenet_kernel, cudaFuncAttributeMaxDynamicSharedMemorySize, SMEM_BYTES);

    cudaMemcpyToSymbolAsync(C0,   d_in[1],   24 * sizeof(float), 0, cudaMemcpyDeviceToDevice, 0);
    cudaMemcpyToSymbolAsync(CK,   d_in[2], 1728 * sizeof(float), 0, cudaMemcpyDeviceToDevice, 0);
    cudaMemcpyToSymbolAsync(CB,   d_in[3],   80 * sizeof(float), 0, cudaMemcpyDeviceToDevice, 0);
    cudaMemcpyToSymbolAsync(IOK,  d_in[4],  576 * sizeof(float), 0, cudaMemcpyDeviceToDevice, 0);
    cudaMemcpyToSymbolAsync(IOB,  d_in[5],   72 * sizeof(float), 0, cudaMemcpyDeviceToDevice, 0);
    cudaMemcpyToSymbolAsync(MIX,  d_in[6],   80 * sizeof(float), 0, cudaMemcpyDeviceToDevice, 0);
    cudaMemcpyToSymbolAsync(MIXB, d_in[7],    1 * sizeof(float), 0, cudaMemcpyDeviceToDevice, 0);

    wavenet_kernel<<<64, NTH, SMEM_BYTES>>>(x, (float*)d_out);
}

// round 3
// speedup vs baseline: 1.3182x; 1.0916x over previous
#include <cuda_runtime.h>
#include <cstdint>

// WaveNet dilated causal conv stack, 2-CTA cluster split per batch element.
// Each cluster rank computes half of every layer's position range; halos are
// exchanged via DSMEM (mapa + ld.shared::cluster) once per layer.

#define NTH 512
#define LBUF 2176
#define FRAME 128
#define TFULL 4096

__device__ __forceinline__ uint32_t s2u(const void* p) {
    return (uint32_t)__cvta_generic_to_shared(p);
}
__device__ __forceinline__ uint32_t mapa_peer(uint32_t a, uint32_t peer) {
    uint32_t r;
    asm volatile("mapa.shared::cluster.u32 %0, %1, %2;" : "=r"(r) : "r"(a), "r"(peer));
    return r;
}
__device__ __forceinline__ float ld_dsm(uint32_t a) {
    float v;
    asm volatile("ld.shared::cluster.f32 %0, [%1];" : "=f"(v) : "r"(a));
    return v;
}
#define CS() do { asm volatile("barrier.cluster.arrive.aligned;" ::: "memory"); \
                  asm volatile("barrier.cluster.wait.aligned;" ::: "memory"); } while(0)

extern __shared__ float smem[];

__global__ __launch_bounds__(NTH) __cluster_dims__(2, 1, 1)
void wavenet_kernel(const float* __restrict__ X,
                    const float* __restrict__ pC0,  const float* __restrict__ pCK,
                    const float* __restrict__ pCB,  const float* __restrict__ pIOK,
                    const float* __restrict__ pIOB, const float* __restrict__ pMIX,
                    const float* __restrict__ pMIXB,
                    float* __restrict__ out)
{
    float* xb   = smem;                       // LBUF
    float* hA   = smem + LBUF;                // 8*LBUF  h[c*LBUF+l]
    float* hB   = smem + 9 * LBUF;            // 8*LBUF
    float* oacc = smem + 17 * LBUF;           // FRAME
    float* C0   = smem + 17 * LBUF + FRAME;   // 24
    float* CK   = C0 + 24;                    // 1728
    float* CB   = CK + 1728;                  // 80
    float* IOK  = CB + 80;                    // 576
    float* IOB  = IOK + 576;                  // 72
    float* MIX  = IOB + 72;                   // 80
    float* MIXB = MIX + 80;                   // 1

    const int tid = threadIdx.x;
    uint32_t rank;
    asm("mov.u32 %0, %%cluster_ctarank;" : "=r"(rank));
    const uint32_t peer = rank ^ 1u;
    const int b = blockIdx.x >> 1;
    const float* x = X + b * TFULL + (TFULL - LBUF);

    // ---- load weights + input into SMEM ----
    for (int k = tid; k < 24;   k += NTH) C0[k]  = pC0[k];
    for (int k = tid; k < 1728; k += NTH) CK[k]  = pCK[k];
    for (int k = tid; k < 80;   k += NTH) CB[k]  = pCB[k];
    for (int k = tid; k < 576;  k += NTH) IOK[k] = pIOK[k];
    for (int k = tid; k < 72;   k += NTH) IOB[k] = pIOB[k];
    for (int k = tid; k < 80;   k += NTH) MIX[k] = pMIX[k];
    if (tid == 0) MIXB[0] = pMIXB[0];
    for (int l = tid; l < LBUF; l += NTH) xb[l] = x[l];
    __syncthreads();
    if (rank && tid < FRAME) oacc[tid] = MIXB[0];
    __syncthreads();

    // ---- layer 0 (fused conv1->8 + relu + mixer + io + x residual) -> hA ----
    {
        const int S = 2, M = (S + LBUF) / 2;     // 1089
        const int lo = rank ? M : S;
        const int hi = rank ? LBUF : M;
        for (int l = lo + tid; l < hi; l += NTH) {
            float x0 = xb[l - 2], x1 = xb[l - 1], x2 = xb[l];
            float acc[8];
#pragma unroll
            for (int co = 0; co < 8; co++) {
                float a = CB[co];
                a = fmaf(x0, C0[co], a);
                a = fmaf(x1, C0[8 + co], a);
                a = fmaf(x2, C0[16 + co], a);
                acc[co] = fmaxf(a, 0.0f);
            }
            if (l >= LBUF - FRAME) {
                float m = 0.0f;
#pragma unroll
                for (int co = 0; co < 8; co++) m = fmaf(acc[co], MIX[co], m);
                oacc[l - (LBUF - FRAME)] += m;
            }
#pragma unroll
            for (int co = 0; co < 8; co++) {
                float a = IOB[co] + x2;
#pragma unroll
                for (int ci = 0; ci < 8; ci++) a = fmaf(acc[ci], IOK[ci * 8 + co], a);
                hA[co * LBUF + l] = a;
            }
        }
    }
    CS();

    // ---- layers 1..8 (fused), ping-pong, halo exchange per layer ----
#pragma unroll
    for (int i = 1; i < 9; i++) {
        const int d  = 1 << i;
        const int S  = 2 * ((2 << i) - 1);
        const int M  = (S + LBUF) / 2;
        const int Sp = 2 * ((1 << i) - 1);       // S_{i-1}
        const int Mp = (Sp + LBUF) / 2;          // M_{i-1}
        float* cur = (i & 1) ? hA : hB;          // output of layer i-1
        float* nxt = (i & 1) ? hB : hA;

        // halo copy from peer into own `cur` buffer
        {
            const int W    = d;                            // 2^i
            const int base = rank ? (Mp - W) : Mp;         // rank1 below Mp, rank0 above
            const uint32_t rbase = mapa_peer(s2u(cur), peer);
            for (int e = tid; e < 8 * W; e += NTH) {
                const int ci = e / W, j = e - ci * W;
                const int idx = ci * LBUF + base + j;
                cur[idx] = ld_dsm(rbase + (uint32_t)idx * 4u);
            }
        }
        __syncthreads();

        const int lo = rank ? M : S;
        const int hi = rank ? LBUF : M;
        for (int l = lo + tid; l < hi; l += NTH) {
            float acc[8], hl[8];
#pragma unroll
            for (int co = 0; co < 8; co++) acc[co] = CB[i * 8 + co];
#pragma unroll
            for (int w = 0; w < 3; w++) {
                const int off = (2 - w) * d;
#pragma unroll
                for (int ci = 0; ci < 8; ci++) {
                    float v = cur[ci * LBUF + l - off];
                    if (w == 2) hl[ci] = v;
#pragma unroll
                    for (int co = 0; co < 8; co++)
                        acc[co] = fmaf(v, CK[(((i - 1) * 3 + w) * 8 + ci) * 8 + co], acc[co]);
                }
            }
#pragma unroll
            for (int co = 0; co < 8; co++) acc[co] = fmaxf(acc[co], 0.0f);
            if (l >= LBUF - FRAME) {
                float m = 0.0f;
#pragma unroll
                for (int co = 0; co < 8; co++) m = fmaf(acc[co], MIX[i * 8 + co], m);
                oacc[l - (LBUF - FRAME)] += m;
            }
#pragma unroll
            for (int co = 0; co < 8; co++) {
                float a = IOB[i * 8 + co] + hl[co];
#pragma unroll
                for (int ci = 0; ci < 8; ci++)
                    a = fmaf(acc[ci], IOK[(i * 8 + ci) * 8 + co], a);
                nxt[co * LBUF + l] = a;
            }
        }
        CS();
    }

    // ---- layer 9: rank1 only; halo strips [1024,1152) and [1536,1599) ----
    if (rank) {
        const uint32_t rbase = mapa_peer(s2u(hA), peer);    // layer 8 output = hA
        for (int e = tid; e < 8 * 128; e += NTH) {
            const int ci = e >> 7, j = e & 127;
            const int idx = ci * LBUF + 1024 + j;
            hA[idx] = ld_dsm(rbase + (uint32_t)idx * 4u);
        }
        for (int e = tid; e < 8 * 63; e += NTH) {
            const int ci = e / 63, j = e - ci * 63;
            const int idx = ci * LBUF + 1536 + j;
            hA[idx] = ld_dsm(rbase + (uint32_t)idx * 4u);
        }
    }
    CS();   // rank0 may exit only after rank1 finished reading its SMEM

    if (rank) {
        const int i = 9, d = 512;
        for (int l = (LBUF - FRAME) + tid; l < LBUF; l += NTH) {
            float acc[8];
#pragma unroll
            for (int co = 0; co < 8; co++) acc[co] = CB[i * 8 + co];
#pragma unroll
            for (int w = 0; w < 3; w++) {
                const int off = (2 - w) * d;
#pragma unroll
                for (int ci = 0; ci < 8; ci++) {
                    float v = hA[ci * LBUF + l - off];
#pragma unroll
                    for (int co = 0; co < 8; co++)
                        acc[co] = fmaf(v, CK[(((i - 1) * 3 + w) * 8 + ci) * 8 + co], acc[co]);
                }
            }
            float m = 0.0f;
#pragma unroll
            for (int co = 0; co < 8; co++) m = fmaf(fmaxf(acc[co], 0.0f), MIX[i * 8 + co], m);
            oacc[l - (LBUF - FRAME)] += m;
        }
        __syncthreads();
        for (int j = tid; j < FRAME; j += NTH) out[b * FRAME + j] = oacc[j];
    }
}

static const int SMEM_BYTES = (17 * LBUF + FRAME + 24 + 1728 + 80 + 576 + 72 + 80 + 1) * (int)sizeof(float);

extern "C" void kernel_launch(void* const* d_in, const int* in_sizes, int n_in,
                              void* d_out, int out_size) {
    (void)in_sizes; (void)n_in; (void)out_size;
    cudaFuncSetAttribute(wavenet_kernel, cudaFuncAttributeMaxDynamicSharedMemorySize, SMEM_BYTES);
    wavenet_kernel<<<128, NTH, SMEM_BYTES>>>(
        (const float*)d_in[0], (const float*)d_in[1], (const float*)d_in[2],
        (const float*)d_in[3], (const float*)d_in[4], (const float*)d_in[5],
        (const float*)d_in[6], (const float*)d_in[7], (float*)d_out);
}

// round 4
// speedup vs baseline: 1.5251x; 1.1569x over previous
#include <cuda_runtime.h>
#include <cstdint>

// WaveNet dilated causal conv stack.
// 2-CTA cluster per batch element (split at even midpoints M_i), fused layers,
// packed f32x2 position-pairs, weights in __constant__ pre-duplicated as pairs.

#define NTH 512
#define LBUF 2176
#define FRAME 128
#define TFULL 4096

typedef unsigned long long u64;

// constant weight bank: each original weight w stored as the pair (w, w)
#define OC0   0
#define OCK   24
#define OCB   1752
#define OIOK  1832
#define OIOB  2408
#define OMIX  2480
#define OMIXB 2560
#define NW    2561

__constant__ u64 Wc[NW];
__device__ u64 Wpack[NW];

__device__ __forceinline__ u64 ffma2(u64 a, u64 b, u64 c) {
    u64 d; asm("fma.rn.f32x2 %0,%1,%2,%3;" : "=l"(d) : "l"(a), "l"(b), "l"(c)); return d;
}
__device__ __forceinline__ u64 fadd2(u64 a, u64 b) {
    u64 d; asm("add.rn.f32x2 %0,%1,%2;" : "=l"(d) : "l"(a), "l"(b)); return d;
}
__device__ __forceinline__ u64 relu2(u64 a) {
    float lo = __uint_as_float((unsigned)(a & 0xffffffffull));
    float hi = __uint_as_float((unsigned)(a >> 32));
    lo = fmaxf(lo, 0.0f); hi = fmaxf(hi, 0.0f);
    return (u64)__float_as_uint(lo) | ((u64)__float_as_uint(hi) << 32);
}

__device__ __forceinline__ uint32_t s2u(const void* p) {
    return (uint32_t)__cvta_generic_to_shared(p);
}
__device__ __forceinline__ uint32_t mapa_peer(uint32_t a, uint32_t peer) {
    uint32_t r;
    asm volatile("mapa.shared::cluster.u32 %0, %1, %2;" : "=r"(r) : "r"(a), "r"(peer));
    return r;
}
__device__ __forceinline__ float ld_dsm(uint32_t a) {
    float v;
    asm volatile("ld.shared::cluster.f32 %0, [%1];" : "=f"(v) : "r"(a));
    return v;
}
#define CS() do { asm volatile("barrier.cluster.arrive.aligned;" ::: "memory"); \
                  asm volatile("barrier.cluster.wait.aligned;" ::: "memory"); } while(0)

// even split point for a layer with valid-start S
#define MSPLIT(S) ((((S) + LBUF) / 2) & ~1)

__global__ void pack_weights(const float* __restrict__ c0,  const float* __restrict__ ck,
                             const float* __restrict__ cb,  const float* __restrict__ iok,
                             const float* __restrict__ iob, const float* __restrict__ mix,
                             const float* __restrict__ mixb) {
    int i = blockIdx.x * blockDim.x + threadIdx.x;
    if (i >= NW) return;
    float v;
    if      (i < OCK)   v = c0[i - OC0];
    else if (i < OCB)   v = ck[i - OCK];
    else if (i < OIOK)  v = cb[i - OCB];
    else if (i < OIOB)  v = iok[i - OIOK];
    else if (i < OMIX)  v = iob[i - OIOB];
    else if (i < OMIXB) v = mix[i - OMIX];
    else                v = mixb[0];
    unsigned u = __float_as_uint(v);
    Wpack[i] = (u64)u | ((u64)u << 32);
}

extern __shared__ float smem[];

__global__ __launch_bounds__(NTH) __cluster_dims__(2, 1, 1)
void wavenet_kernel(const float* __restrict__ X, float* __restrict__ out)
{
    float* xb   = smem;              // LBUF
    float* hA   = smem + LBUF;       // 8*LBUF   h[c*LBUF + l]
    float* hB   = smem + 9 * LBUF;   // 8*LBUF
    float* oacc = smem + 17 * LBUF;  // FRAME

    const int tid = threadIdx.x;
    uint32_t rank;
    asm("mov.u32 %0, %%cluster_ctarank;" : "=r"(rank));
    const uint32_t peer = rank ^ 1u;
    const int b = blockIdx.x >> 1;
    const float* x = X + b * TFULL + (TFULL - LBUF);

    for (int l = tid; l < LBUF; l += NTH) xb[l] = x[l];
    if (rank && tid < FRAME) {
        float mb = __uint_as_float((unsigned)(Wc[OMIXB] & 0xffffffffull));
        oacc[tid] = mb;
    }
    __syncthreads();

    // ---- layer 0 (fused conv1->8 + relu + mixer + io + x residual) -> hA ----
    {
        const int S = 2, M = MSPLIT(S);                 // 1088
        const int lo = rank ? M : S;
        const int hi = rank ? LBUF : M;
        for (int l = lo + 2 * tid; l < hi; l += 2 * NTH) {
            u64 A = *(const u64*)&xb[l - 2];            // (x[l-2], x[l-1])
            u64 B = *(const u64*)&xb[l];                // (x[l],   x[l+1])
            u64 x1p = (A >> 32) | (B << 32);            // (x[l-1], x[l])
            u64 acc[8];
#pragma unroll
            for (int co = 0; co < 8; co++) {
                u64 a = Wc[OCB + co];
                a = ffma2(A,   Wc[OC0 + co],      a);
                a = ffma2(x1p, Wc[OC0 + 8 + co],  a);
                a = ffma2(B,   Wc[OC0 + 16 + co], a);
                acc[co] = relu2(a);
            }
            if (l >= LBUF - FRAME) {
                u64 m = 0;
#pragma unroll
                for (int co = 0; co < 8; co++) m = ffma2(acc[co], Wc[OMIX + co], m);
                u64* op = (u64*)&oacc[l - (LBUF - FRAME)];
                *op = fadd2(*op, m);
            }
#pragma unroll
            for (int co = 0; co < 8; co++) {
                u64 a = fadd2(Wc[OIOB + co], B);
#pragma unroll
                for (int ci = 0; ci < 8; ci++) a = ffma2(acc[ci], Wc[OIOK + ci * 8 + co], a);
                *(u64*)(hA + co * LBUF + l) = a;
            }
        }
    }
    CS();

    // ---- layers 1..8 (fused), ping-pong, halo exchange per layer ----
#pragma unroll
    for (int i = 1; i < 9; i++) {
        const int d  = 1 << i;
        const int S  = 2 * ((2 << i) - 1);
        const int M  = MSPLIT(S);
        const int Sp = 2 * ((1 << i) - 1);
        const int Mp = MSPLIT(Sp);
        float* cur = (i & 1) ? hA : hB;
        float* nxt = (i & 1) ? hB : hA;

        // halo: rank0 pulls [Mp, Mp+d) (owned by rank1); rank1 pulls [Mp-d, Mp)
        {
            const int W    = d;
            const int base = rank ? (Mp - W) : Mp;
            const uint32_t rbase = mapa_peer(s2u(cur), peer);
            for (int e = tid; e < 8 * W; e += NTH) {
                const int ci = e / W, j = e - ci * W;
                const int idx = ci * LBUF + base + j;
                cur[idx] = ld_dsm(rbase + (uint32_t)idx * 4u);
            }
        }
        __syncthreads();

        const int lo = rank ? M : S;
        const int hi = rank ? LBUF : M;
        for (int l = lo + 2 * tid; l < hi; l += 2 * NTH) {
            u64 acc[8], hl[8];
#pragma unroll
            for (int co = 0; co < 8; co++) acc[co] = Wc[OCB + i * 8 + co];
#pragma unroll
            for (int w = 0; w < 3; w++) {
                const int off = (2 - w) * d;
#pragma unroll
                for (int ci = 0; ci < 8; ci++) {
                    u64 v = *(const u64*)(cur + ci * LBUF + (l - off));
                    if (w == 2) hl[ci] = v;
#pragma unroll
                    for (int co = 0; co < 8; co++)
                        acc[co] = ffma2(v, Wc[OCK + (((i - 1) * 3 + w) * 8 + ci) * 8 + co], acc[co]);
                }
            }
#pragma unroll
            for (int co = 0; co < 8; co++) acc[co] = relu2(acc[co]);
            if (l >= LBUF - FRAME) {
                u64 m = 0;
#pragma unroll
                for (int co = 0; co < 8; co++) m = ffma2(acc[co], Wc[OMIX + i * 8 + co], m);
                u64* op = (u64*)&oacc[l - (LBUF - FRAME)];
                *op = fadd2(*op, m);
            }
#pragma unroll
            for (int co = 0; co < 8; co++) {
                u64 a = fadd2(Wc[OIOB + i * 8 + co], hl[co]);
#pragma unroll
                for (int ci = 0; ci < 8; ci++)
                    a = ffma2(acc[ci], Wc[OIOK + (i * 8 + ci) * 8 + co], a);
                *(u64*)(nxt + co * LBUF + l) = a;
            }
        }
        CS();
    }

    // ---- layer 9 halo: rank1 needs hA [1024,1152) and [1536, M8) from rank0 ----
    const int M8 = MSPLIT(1022);   // 1598
    if (rank) {
        const uint32_t rbase = mapa_peer(s2u(hA), peer);   // layer-8 output = hA
        for (int e = tid; e < 8 * 128; e += NTH) {
            const int ci = e >> 7, j = e & 127;
            const int idx = ci * LBUF + 1024 + j;
            hA[idx] = ld_dsm(rbase + (uint32_t)idx * 4u);
        }
        const int W2 = M8 - 1536;                          // 62
        for (int e = tid; e < 8 * W2; e += NTH) {
            const int ci = e / W2, j = e - ci * W2;
            const int idx = ci * LBUF + 1536 + j;
            hA[idx] = ld_dsm(rbase + (uint32_t)idx * 4u);
        }
    }
    CS();   // rank0 must not exit before rank1 reads its SMEM

    if (rank) {
        __syncthreads();
        const int i = 9, d = 512;
        for (int l = (LBUF - FRAME) + 2 * tid; l < LBUF; l += 2 * NTH) {
            u64 acc[8];
#pragma unroll
            for (int co = 0; co < 8; co++) acc[co] = Wc[OCB + i * 8 + co];
#pragma unroll
            for (int w = 0; w < 3; w++) {
                const int off = (2 - w) * d;
#pragma unroll
                for (int ci = 0; ci < 8; ci++) {
                    u64 v = *(const u64*)(hA + ci * LBUF + (l - off));
#pragma unroll
                    for (int co = 0; co < 8; co++)
                        acc[co] = ffma2(v, Wc[OCK + (((i - 1) * 3 + w) * 8 + ci) * 8 + co], acc[co]);
                }
            }
            u64 m = 0;
#pragma unroll
            for (int co = 0; co < 8; co++) m = ffma2(relu2(acc[co]), Wc[OMIX + i * 8 + co], m);
            u64* op = (u64*)&oacc[l - (LBUF - FRAME)];
            *op = fadd2(*op, m);
        }
        __syncthreads();
        for (int j = tid; j < FRAME; j += NTH) out[b * FRAME + j] = oacc[j];
    }
}

static const int SMEM_BYTES = (17 * LBUF + FRAME) * (int)sizeof(float);

extern "C" void kernel_launch(void* const* d_in, const int* in_sizes, int n_in,
                              void* d_out, int out_size) {
    (void)in_sizes; (void)n_in; (void)out_size;
    cudaFuncSetAttribute(wavenet_kernel, cudaFuncAttributeMaxDynamicSharedMemorySize, SMEM_BYTES);

    pack_weights<<<(NW + 511) / 512, 512>>>(
        (const float*)d_in[1], (const float*)d_in[2], (const float*)d_in[3],
        (const float*)d_in[4], (const float*)d_in[5], (const float*)d_in[6],
        (const float*)d_in[7]);

    void* wp = nullptr;
    cudaGetSymbolAddress(&wp, Wpack);
    cudaMemcpyToSymbolAsync(Wc, wp, NW * sizeof(u64), 0, cudaMemcpyDeviceToDevice, 0);

    wavenet_kernel<<<128, NTH, SMEM_BYTES>>>((const float*)d_in[0], (float*)d_out);
}

// round 5
// speedup vs baseline: 1.9154x; 1.2559x over previous
#include <cuda_runtime.h>
#include <cstdint>

// WaveNet dilated causal conv stack.
// 2-CTA cluster per batch element, fused conv+io layers, ping-pong h in SMEM,
// scalar FFMA on position PAIRS (float2 loads/stores, weights via constant/LDCU).

#define NTH 544
#define LBUF 2176
#define FRAME 128
#define TFULL 4096

// scalar constant weight bank
#define OC0   0
#define OCK   24
#define OCB   1752
#define OIOK  1832
#define OIOB  2408
#define OMIX  2480
#define OMIXB 2560
#define NW    2561

__constant__ float Wc[NW];
__device__ float Wstage[NW];

__device__ __forceinline__ uint32_t s2u(const void* p) {
    return (uint32_t)__cvta_generic_to_shared(p);
}
__device__ __forceinline__ uint32_t mapa_peer(uint32_t a, uint32_t peer) {
    uint32_t r;
    asm volatile("mapa.shared::cluster.u32 %0, %1, %2;" : "=r"(r) : "r"(a), "r"(peer));
    return r;
}
__device__ __forceinline__ float ld_dsm(uint32_t a) {
    float v;
    asm volatile("ld.shared::cluster.f32 %0, [%1];" : "=f"(v) : "r"(a));
    return v;
}
#define CS() do { asm volatile("barrier.cluster.arrive.aligned;" ::: "memory"); \
                  asm volatile("barrier.cluster.wait.aligned;" ::: "memory"); } while(0)

// even split point for a layer with valid-start S
#define MSPLIT(S) ((((S) + LBUF) / 2) & ~1)

__global__ void pack_weights(const float* __restrict__ c0,  const float* __restrict__ ck,
                             const float* __restrict__ cb,  const float* __restrict__ iok,
                             const float* __restrict__ iob, const float* __restrict__ mix,
                             const float* __restrict__ mixb) {
    int i = blockIdx.x * blockDim.x + threadIdx.x;
    if (i >= NW) return;
    float v;
    if      (i < OCK)   v = c0[i - OC0];
    else if (i < OCB)   v = ck[i - OCK];
    else if (i < OIOK)  v = cb[i - OCB];
    else if (i < OIOB)  v = iok[i - OIOK];
    else if (i < OMIX)  v = iob[i - OIOB];
    else if (i < OMIXB) v = mix[i - OMIX];
    else                v = mixb[0];
    Wstage[i] = v;
}

extern __shared__ float smem[];

__global__ __launch_bounds__(NTH) __cluster_dims__(2, 1, 1)
void wavenet_kernel(const float* __restrict__ X, float* __restrict__ out)
{
    float* xb   = smem;              // LBUF
    float* hA   = smem + LBUF;       // 8*LBUF   h[c*LBUF + l]
    float* hB   = smem + 9 * LBUF;   // 8*LBUF
    float* oacc = smem + 17 * LBUF;  // FRAME

    const int tid = threadIdx.x;
    uint32_t rank;
    asm("mov.u32 %0, %%cluster_ctarank;" : "=r"(rank));
    const uint32_t peer = rank ^ 1u;
    const int b = blockIdx.x >> 1;
    const float* x = X + b * TFULL + (TFULL - LBUF);

    for (int l = tid; l < LBUF; l += NTH) xb[l] = x[l];
    if (rank && tid < FRAME) oacc[tid] = Wc[OMIXB];
    __syncthreads();

    // ---- layer 0 (fused conv1->8 + relu + mixer + io + x residual) -> hA ----
    {
        const int S = 2, M = MSPLIT(S);                 // 1088
        const int lo = rank ? M : S;
        const int hi = rank ? LBUF : M;
        for (int l = lo + 2 * tid; l < hi; l += 2 * NTH) {
            float2 A = *(const float2*)&xb[l - 2];      // x[l-2], x[l-1]
            float2 B = *(const float2*)&xb[l];          // x[l],   x[l+1]
            float acc0[8], acc1[8];
#pragma unroll
            for (int co = 0; co < 8; co++) {
                float w0 = Wc[OC0 + co], w1 = Wc[OC0 + 8 + co], w2 = Wc[OC0 + 16 + co];
                float bb = Wc[OCB + co];
                float a0 = fmaf(B.x, w2, fmaf(A.y, w1, fmaf(A.x, w0, bb)));
                float a1 = fmaf(B.y, w2, fmaf(B.x, w1, fmaf(A.y, w0, bb)));
                acc0[co] = fmaxf(a0, 0.0f);
                acc1[co] = fmaxf(a1, 0.0f);
            }
            if (l >= LBUF - FRAME) {
                float m0 = 0.0f, m1 = 0.0f;
#pragma unroll
                for (int co = 0; co < 8; co++) {
                    float mw = Wc[OMIX + co];
                    m0 = fmaf(acc0[co], mw, m0);
                    m1 = fmaf(acc1[co], mw, m1);
                }
                oacc[l - (LBUF - FRAME)]     += m0;
                oacc[l - (LBUF - FRAME) + 1] += m1;
            }
#pragma unroll
            for (int co = 0; co < 8; co++) {
                float bb = Wc[OIOB + co];
                float a0 = bb + B.x, a1 = bb + B.y;
#pragma unroll
                for (int ci = 0; ci < 8; ci++) {
                    float wk = Wc[OIOK + ci * 8 + co];
                    a0 = fmaf(acc0[ci], wk, a0);
                    a1 = fmaf(acc1[ci], wk, a1);
                }
                *(float2*)(hA + co * LBUF + l) = make_float2(a0, a1);
            }
        }
    }
    CS();

    // ---- layers 1..8 (fused), ping-pong, halo exchange per layer ----
#pragma unroll
    for (int i = 1; i < 9; i++) {
        const int d  = 1 << i;
        const int S  = 2 * ((2 << i) - 1);
        const int M  = MSPLIT(S);
        const int Sp = 2 * ((1 << i) - 1);
        const int Mp = MSPLIT(Sp);
        float* cur = (i & 1) ? hA : hB;
        float* nxt = (i & 1) ? hB : hA;

        // halo: rank0 pulls [Mp, Mp+d); rank1 pulls [Mp-d, Mp)
        {
            const int W    = d;
            const int base = rank ? (Mp - W) : Mp;
            const uint32_t rbase = mapa_peer(s2u(cur), peer);
            for (int e = tid; e < 8 * W; e += NTH) {
                const int ci = e / W, j = e - ci * W;
                const int idx = ci * LBUF + base + j;
                cur[idx] = ld_dsm(rbase + (uint32_t)idx * 4u);
            }
        }
        __syncthreads();

        const int lo = rank ? M : S;
        const int hi = rank ? LBUF : M;
        for (int l = lo + 2 * tid; l < hi; l += 2 * NTH) {
            float acc0[8], acc1[8], hl0[8], hl1[8];
#pragma unroll
            for (int co = 0; co < 8; co++) { acc0[co] = Wc[OCB + i * 8 + co]; acc1[co] = acc0[co]; }
#pragma unroll
            for (int w = 0; w < 3; w++) {
                const int off = (2 - w) * d;
#pragma unroll
                for (int ci = 0; ci < 8; ci++) {
                    float2 v = *(const float2*)(cur + ci * LBUF + (l - off));
                    if (w == 2) { hl0[ci] = v.x; hl1[ci] = v.y; }
#pragma unroll
                    for (int co = 0; co < 8; co++) {
                        float wk = Wc[OCK + (((i - 1) * 3 + w) * 8 + ci) * 8 + co];
                        acc0[co] = fmaf(v.x, wk, acc0[co]);
                        acc1[co] = fmaf(v.y, wk, acc1[co]);
                    }
                }
            }
#pragma unroll
            for (int co = 0; co < 8; co++) {
                acc0[co] = fmaxf(acc0[co], 0.0f);
                acc1[co] = fmaxf(acc1[co], 0.0f);
            }
            if (l >= LBUF - FRAME) {
                float m0 = 0.0f, m1 = 0.0f;
#pragma unroll
                for (int co = 0; co < 8; co++) {
                    float mw = Wc[OMIX + i * 8 + co];
                    m0 = fmaf(acc0[co], mw, m0);
                    m1 = fmaf(acc1[co], mw, m1);
                }
                oacc[l - (LBUF - FRAME)]     += m0;
                oacc[l - (LBUF - FRAME) + 1] += m1;
            }
#pragma unroll
            for (int co = 0; co < 8; co++) {
                float bb = Wc[OIOB + i * 8 + co];
                float a0 = bb + hl0[co], a1 = bb + hl1[co];
#pragma unroll
                for (int ci = 0; ci < 8; ci++) {
                    float wk = Wc[OIOK + (i * 8 + ci) * 8 + co];
                    a0 = fmaf(acc0[ci], wk, a0);
                    a1 = fmaf(acc1[ci], wk, a1);
                }
                *(float2*)(nxt + co * LBUF + l) = make_float2(a0, a1);
            }
        }
        CS();
    }

    // ---- layer 9 halo: rank1 needs hA [1024,1152) and [1536, M8) from rank0 ----
    const int M8 = MSPLIT(1022);   // 1598
    if (rank) {
        const uint32_t rbase = mapa_peer(s2u(hA), peer);   // layer-8 output = hA
        for (int e = tid; e < 8 * 128; e += NTH) {
            const int ci = e >> 7, j = e & 127;
            const int idx = ci * LBUF + 1024 + j;
            hA[idx] = ld_dsm(rbase + (uint32_t)idx * 4u);
        }
        const int W2 = M8 - 1536;                          // 62
        for (int e = tid; e < 8 * W2; e += NTH) {
            const int ci = e / W2, j = e - ci * W2;
            const int idx = ci * LBUF + 1536 + j;
            hA[idx] = ld_dsm(rbase + (uint32_t)idx * 4u);
        }
    }
    CS();   // rank0 must not exit before rank1 reads its SMEM

    if (rank) {
        __syncthreads();
        const int i = 9, d = 512;
        for (int l = (LBUF - FRAME) + 2 * tid; l < LBUF; l += 2 * NTH) {
            float acc0[8], acc1[8];
#pragma unroll
            for (int co = 0; co < 8; co++) { acc0[co] = Wc[OCB + i * 8 + co]; acc1[co] = acc0[co]; }
#pragma unroll
            for (int w = 0; w < 3; w++) {
                const int off = (2 - w) * d;
#pragma unroll
                for (int ci = 0; ci < 8; ci++) {
                    float2 v = *(const float2*)(hA + ci * LBUF + (l - off));
#pragma unroll
                    for (int co = 0; co < 8; co++) {
                        float wk = Wc[OCK + (((i - 1) * 3 + w) * 8 + ci) * 8 + co];
                        acc0[co] = fmaf(v.x, wk, acc0[co]);
                        acc1[co] = fmaf(v.y, wk, acc1[co]);
                    }
                }
            }
            float m0 = 0.0f, m1 = 0.0f;
#pragma unroll
            for (int co = 0; co < 8; co++) {
                float mw = Wc[OMIX + i * 8 + co];
                m0 = fmaf(fmaxf(acc0[co], 0.0f), mw, m0);
                m1 = fmaf(fmaxf(acc1[co], 0.0f), mw, m1);
            }
            oacc[l - (LBUF - FRAME)]     += m0;
            oacc[l - (LBUF - FRAME) + 1] += m1;
        }
        __syncthreads();
        for (int j = tid; j < FRAME; j += NTH) out[b * FRAME + j] = oacc[j];
    }
}

static const int SMEM_BYTES = (17 * LBUF + FRAME) * (int)sizeof(float);

extern "C" void kernel_launch(void* const* d_in, const int* in_sizes, int n_in,
                              void* d_out, int out_size) {
    (void)in_sizes; (void)n_in; (void)out_size;
    cudaFuncSetAttribute(wavenet_kernel, cudaFuncAttributeMaxDynamicSharedMemorySize, SMEM_BYTES);

    pack_weights<<<(NW + 511) / 512, 512>>>(
        (const float*)d_in[1], (const float*)d_in[2], (const float*)d_in[3],
        (const float*)d_in[4], (const float*)d_in[5], (const float*)d_in[6],
        (const float*)d_in[7]);

    void* wp = nullptr;
    cudaGetSymbolAddress(&wp, Wstage);
    cudaMemcpyToSymbolAsync(Wc, wp, NW * sizeof(float), 0, cudaMemcpyDeviceToDevice, 0);

    wavenet_kernel<<<128, NTH, SMEM_BYTES>>>((const float*)d_in[0], (float*)d_out);
}